// round 3
// baseline (speedup 1.0000x reference)
#include <cuda_runtime.h>
#include <cuda_fp16.h>
#include <cstdint>

#define M_DIM 8192
#define K_DIM 4096
#define N_DIM 11008

// ---------------- scratch (device globals; no runtime allocation) ----------
__device__ __half g_Ah[(size_t)M_DIM * K_DIM];   // A in fp16, [M, K] row-major
__device__ __half g_Wt[(size_t)N_DIM * K_DIM];   // W^T dequant fp16, [N, K] row-major

// ---------------- fused pre-pass: A fp32->fp16  +  int4 dequant->Wt[N,K] ---
// blocks [0, A_BLOCKS): convert A (each thread one float4)
// blocks [A_BLOCKS, ...): dequant W, 64k x 32n per block
static constexpr int A_BLOCKS = (int)(((size_t)M_DIM * K_DIM / 4) / 256);   // 32768
static constexpr int W_BLOCKS = (K_DIM / 64) * (N_DIM / 32);                 // 22016

__global__ void prep_kernel(const float* __restrict__ a, const int* __restrict__ w,
                            const float* __restrict__ scale, const int* __restrict__ zp) {
    __shared__ int sw[32][33];
    __shared__ float ssc[32];
    __shared__ float szp[32];
    int t = threadIdx.x;
    if (blockIdx.x < A_BLOCKS) {
        size_t i = (size_t)blockIdx.x * 256 + t;
        float4 v = reinterpret_cast<const float4*>(a)[i];
        __half2 h0 = __floats2half2_rn(v.x, v.y);
        __half2 h1 = __floats2half2_rn(v.z, v.w);
        uint2 o;
        o.x = *reinterpret_cast<uint32_t*>(&h0);
        o.y = *reinterpret_cast<uint32_t*>(&h1);
        reinterpret_cast<uint2*>(g_Ah)[i] = o;
        return;
    }
    int b = blockIdx.x - A_BLOCKS;
    int kt = b & 63;                   // 0..63 (64 k per tile; group = kt>>1 since 128 = 2*64)
    int nt = b >> 6;                   // 0..343
    int kp0 = kt * 32, n0 = nt * 32;
    int g = kt >> 1;
    for (int i = t; i < 1024; i += 256) {
        int r = i >> 5, c = i & 31;
        sw[r][c] = w[(size_t)(kp0 + r) * N_DIM + (n0 + c)];
    }
    if (t < 32) {
        ssc[t] = scale[(size_t)g * N_DIM + n0 + t];
        szp[t] = (float)zp[(size_t)g * N_DIM + n0 + t];
    }
    __syncthreads();
    int nl = t >> 3;            // local n 0..31
    int kq = (t & 7) * 4;       // local packed-row start (4 packed rows = 8 k)
    float sc = ssc[nl], z = szp[nl];
    __half2 outv[4];
#pragma unroll
    for (int j = 0; j < 4; j++) {
        int wv = sw[kq + j][nl];
        outv[j] = __floats2half2_rn(((float)(wv & 0xF) - z) * sc,         // k even (low nibble)
                                    ((float)((wv >> 4) & 0xF) - z) * sc); // k odd  (high nibble)
    }
    size_t off = (size_t)(n0 + nl) * K_DIM + (size_t)kt * 64 + kq * 2;
    *reinterpret_cast<float4*>(&g_Wt[off]) = *reinterpret_cast<float4*>(outv);
}

// ---------------- main GEMM: mma.sync m16n8k16, cp.async pipeline ----------
// Non-'a' PTX only (harness lowers through compute_103 which bars tcgen05/TMA).
// BM=128 x BN=256, 8 warps in 2x4, warp tile 64x64 (FLOP/smem-byte = 32).
static constexpr int BM = 128, BN = 256, BK = 32, STAGES = 4;
static constexpr int ROW_HALFS = 40;                 // 32 data + 8 pad -> 80B row stride
static constexpr int ROW_BYTES = ROW_HALFS * 2;      // 80
static constexpr int A_STAGE_BYTES = BM * ROW_BYTES;              // 10240
static constexpr int B_STAGE_BYTES = BN * ROW_BYTES;              // 20480
static constexpr int SB_OFF = STAGES * A_STAGE_BYTES;             // 40960
static constexpr int GEMM_SMEM = SB_OFF + STAGES * B_STAGE_BYTES; // 122880
static constexpr int TM_TILES = M_DIM / BM;   // 64
static constexpr int TN_TILES = N_DIM / BN;   // 43
static constexpr int KITERS = K_DIM / BK;     // 128

__device__ __forceinline__ uint32_t smem_u32(const void* p) {
    uint32_t a;
    asm("{ .reg .u64 t; cvta.to.shared.u64 t, %1; cvt.u32.u64 %0, t; }" : "=r"(a) : "l"(p));
    return a;
}

#define CP_ASYNC_16(dst, src) \
    asm volatile("cp.async.cg.shared.global [%0], [%1], 16;" :: "r"(dst), "l"(src))
#define CP_ASYNC_COMMIT() asm volatile("cp.async.commit_group;")
#define CP_ASYNC_WAIT2()  asm volatile("cp.async.wait_group 2;")

#define LDSM_X4(r0, r1, r2, r3, addr) \
    asm volatile("ldmatrix.sync.aligned.m8n8.x4.shared.b16 {%0,%1,%2,%3}, [%4];" \
                 : "=r"(r0), "=r"(r1), "=r"(r2), "=r"(r3) : "r"(addr))

#define MMA_16816(c, a0, a1, a2, a3, b0, b1) \
    asm volatile("mma.sync.aligned.m16n8k16.row.col.f32.f16.f16.f32 " \
                 "{%0,%1,%2,%3}, {%4,%5,%6,%7}, {%8,%9}, {%0,%1,%2,%3};" \
                 : "+f"((c)[0]), "+f"((c)[1]), "+f"((c)[2]), "+f"((c)[3]) \
                 : "r"(a0), "r"(a1), "r"(a2), "r"(a3), "r"(b0), "r"(b1))

__global__ void __launch_bounds__(256, 1) gemm_kernel(float* __restrict__ out) {
    extern __shared__ __align__(128) char smem[];
    uint32_t sb = smem_u32(smem);
    int tid = threadIdx.x, wid = tid >> 5, lane = tid & 31;

    // GROUP_M=8 tile ordering for L2 reuse (A 8MB + B 86MB < 126MB L2)
    constexpr int GROUP_M = 8;
    int pid = blockIdx.x;
    int group_size = GROUP_M * TN_TILES;
    int group_id = pid / group_size;
    int pid_m = group_id * GROUP_M + (pid % GROUP_M);
    int pid_n = (pid % group_size) / GROUP_M;
    int m0 = pid_m * BM, n0 = pid_n * BN;

    // warp grid 2 (m) x 4 (n); warp tile 64 x 64
    int wm = wid & 1, wn = wid >> 1;
    int m0w = wm * 64, n0w = wn * 64;

    // --- cp.async chunk ownership ---
    // A: 128 rows x 4 chunks(16B) = 512 chunks -> threads tid, tid+256
    // B: 256 rows x 4 chunks      = 1024 chunks -> tid, +256, +512, +768
    int rA = tid >> 2, cC = tid & 3;
    const __half* gA0 = &g_Ah[(size_t)(m0 + rA) * K_DIM + cC * 8];
    const __half* gA1 = &g_Ah[(size_t)(m0 + rA + 64) * K_DIM + cC * 8];
    const __half* gB0 = &g_Wt[(size_t)(n0 + rA) * K_DIM + cC * 8];
    const __half* gB1 = &g_Wt[(size_t)(n0 + rA + 64) * K_DIM + cC * 8];
    const __half* gB2 = &g_Wt[(size_t)(n0 + rA + 128) * K_DIM + cC * 8];
    const __half* gB3 = &g_Wt[(size_t)(n0 + rA + 192) * K_DIM + cC * 8];
    uint32_t sA0 = sb + rA * ROW_BYTES + cC * 16;
    uint32_t sA1 = sA0 + 64 * ROW_BYTES;
    uint32_t sB0 = sb + SB_OFF + rA * ROW_BYTES + cC * 16;
    uint32_t sB1 = sB0 + 64 * ROW_BYTES;
    uint32_t sB2 = sB0 + 128 * ROW_BYTES;
    uint32_t sB3 = sB0 + 192 * ROW_BYTES;

    // --- ldmatrix per-lane base addresses (stage-relative) ---
    int lrow = lane & 15;          // row within 16-row matrix pair
    int lcol8 = lane >> 4;         // 0/1 -> k offset 0/8
    uint32_t aAddrBase = sb + (m0w + lrow) * ROW_BYTES + lcol8 * 16;
    uint32_t bAddrBase = sb + SB_OFF + (n0w + lrow) * ROW_BYTES + lcol8 * 16;

    float acc[4][8][4];
#pragma unroll
    for (int mt = 0; mt < 4; mt++)
#pragma unroll
        for (int nt = 0; nt < 8; nt++)
#pragma unroll
            for (int j = 0; j < 4; j++) acc[mt][nt][j] = 0.f;

    // --- prologue: stages 0..2 ---
#pragma unroll
    for (int s = 0; s < STAGES - 1; s++) {
        int koff = s * BK;
        uint32_t soA = s * A_STAGE_BYTES, soB = s * B_STAGE_BYTES;
        CP_ASYNC_16(sA0 + soA, gA0 + koff);
        CP_ASYNC_16(sA1 + soA, gA1 + koff);
        CP_ASYNC_16(sB0 + soB, gB0 + koff);
        CP_ASYNC_16(sB1 + soB, gB1 + koff);
        CP_ASYNC_16(sB2 + soB, gB2 + koff);
        CP_ASYNC_16(sB3 + soB, gB3 + koff);
        CP_ASYNC_COMMIT();
    }

    for (int kt = 0; kt < KITERS; kt++) {
        CP_ASYNC_WAIT2();
        __syncthreads();

        if (kt + STAGES - 1 < KITERS) {
            int s = (kt + STAGES - 1) & (STAGES - 1);
            int koff = (kt + STAGES - 1) * BK;
            uint32_t soA = s * A_STAGE_BYTES, soB = s * B_STAGE_BYTES;
            CP_ASYNC_16(sA0 + soA, gA0 + koff);
            CP_ASYNC_16(sA1 + soA, gA1 + koff);
            CP_ASYNC_16(sB0 + soB, gB0 + koff);
            CP_ASYNC_16(sB1 + soB, gB1 + koff);
            CP_ASYNC_16(sB2 + soB, gB2 + koff);
            CP_ASYNC_16(sB3 + soB, gB3 + koff);
            CP_ASYNC_COMMIT();
        } else {
            CP_ASYNC_COMMIT();
        }

        uint32_t soA = (kt & (STAGES - 1)) * A_STAGE_BYTES;
        uint32_t soB = (kt & (STAGES - 1)) * B_STAGE_BYTES;
#pragma unroll
        for (int ks = 0; ks < 2; ks++) {
            uint32_t kOff = ks * 32;   // 16 halfs = 32 bytes
            uint32_t a_frag[4][4];
#pragma unroll
            for (int mt = 0; mt < 4; mt++)
                LDSM_X4(a_frag[mt][0], a_frag[mt][1], a_frag[mt][2], a_frag[mt][3],
                        aAddrBase + soA + mt * 16 * ROW_BYTES + kOff);
#pragma unroll
            for (int nq = 0; nq < 4; nq++) {     // 16 n per ldmatrix.x4
                uint32_t b0, b1, b2, b3;
                LDSM_X4(b0, b1, b2, b3, bAddrBase + soB + nq * 16 * ROW_BYTES + kOff);
#pragma unroll
                for (int mt = 0; mt < 4; mt++) {
                    MMA_16816(acc[mt][2 * nq], a_frag[mt][0], a_frag[mt][1],
                              a_frag[mt][2], a_frag[mt][3], b0, b2);
                    MMA_16816(acc[mt][2 * nq + 1], a_frag[mt][0], a_frag[mt][1],
                              a_frag[mt][2], a_frag[mt][3], b1, b3);
                }
            }
        }
    }

    // --- epilogue ---
    int gq = lane >> 2, t4 = lane & 3;
#pragma unroll
    for (int mt = 0; mt < 4; mt++) {
        int mrow0 = m0 + m0w + mt * 16 + gq;
#pragma unroll
        for (int nt = 0; nt < 8; nt++) {
            int ncol = n0 + n0w + nt * 8 + t4 * 2;
            float2 v0 = make_float2(acc[mt][nt][0], acc[mt][nt][1]);
            float2 v1 = make_float2(acc[mt][nt][2], acc[mt][nt][3]);
            *reinterpret_cast<float2*>(&out[(size_t)mrow0 * N_DIM + ncol]) = v0;
            *reinterpret_cast<float2*>(&out[(size_t)(mrow0 + 8) * N_DIM + ncol]) = v1;
        }
    }
}

// ---------------- host launch ----------------------------------------------
extern "C" void kernel_launch(void* const* d_in, const int* in_sizes, int n_in,
                              void* d_out, int out_size) {
    const float* A = (const float*)d_in[0];
    const int*   W = (const int*)d_in[1];
    const float* S = (const float*)d_in[2];
    const int*   Z = (const int*)d_in[3];
    float* out = (float*)d_out;

    cudaFuncSetAttribute(gemm_kernel, cudaFuncAttributeMaxDynamicSharedMemorySize, GEMM_SMEM);

    prep_kernel<<<A_BLOCKS + W_BLOCKS, 256>>>(A, W, S, Z);
    gemm_kernel<<<TM_TILES * TN_TILES, 256, GEMM_SMEM>>>(out);
}

// round 4
// speedup vs baseline: 1.2309x; 1.2309x over previous
#include <cuda_runtime.h>
#include <cuda_fp16.h>
#include <cstdint>

#define M_DIM 8192
#define K_DIM 4096
#define N_DIM 11008

// ---------------- scratch (device globals; no runtime allocation) ----------
__device__ __half g_Ah[(size_t)M_DIM * K_DIM];   // A in fp16, [M, K] row-major
__device__ __half g_Wt[(size_t)N_DIM * K_DIM];   // W^T dequant fp16, [N, K] row-major

// ---------------- fused pre-pass: A fp32->fp16  +  int4 dequant->Wt[N,K] ---
static constexpr int A_BLOCKS = (int)(((size_t)M_DIM * K_DIM / 4) / 256);   // 32768
static constexpr int W_BLOCKS = (K_DIM / 64) * (N_DIM / 32);                 // 22016

__global__ void prep_kernel(const float* __restrict__ a, const int* __restrict__ w,
                            const float* __restrict__ scale, const int* __restrict__ zp) {
    __shared__ int sw[32][33];
    __shared__ float ssc[32];
    __shared__ float szp[32];
    int t = threadIdx.x;
    if (blockIdx.x < A_BLOCKS) {
        size_t i = (size_t)blockIdx.x * 256 + t;
        float4 v = reinterpret_cast<const float4*>(a)[i];
        __half2 h0 = __floats2half2_rn(v.x, v.y);
        __half2 h1 = __floats2half2_rn(v.z, v.w);
        uint2 o;
        o.x = *reinterpret_cast<uint32_t*>(&h0);
        o.y = *reinterpret_cast<uint32_t*>(&h1);
        reinterpret_cast<uint2*>(g_Ah)[i] = o;
        return;
    }
    int b = blockIdx.x - A_BLOCKS;
    int kt = b & 63;                   // 64 k per tile; group = kt>>1 (gs=128)
    int nt = b >> 6;
    int kp0 = kt * 32, n0 = nt * 32;
    int g = kt >> 1;
    for (int i = t; i < 1024; i += 256) {
        int r = i >> 5, c = i & 31;
        sw[r][c] = w[(size_t)(kp0 + r) * N_DIM + (n0 + c)];
    }
    if (t < 32) {
        ssc[t] = scale[(size_t)g * N_DIM + n0 + t];
        szp[t] = (float)zp[(size_t)g * N_DIM + n0 + t];
    }
    __syncthreads();
    int nl = t >> 3;
    int kq = (t & 7) * 4;
    float sc = ssc[nl], z = szp[nl];
    __half2 outv[4];
#pragma unroll
    for (int j = 0; j < 4; j++) {
        int wv = sw[kq + j][nl];
        outv[j] = __floats2half2_rn(((float)(wv & 0xF) - z) * sc,
                                    ((float)((wv >> 4) & 0xF) - z) * sc);
    }
    size_t off = (size_t)(n0 + nl) * K_DIM + (size_t)kt * 64 + kq * 2;
    *reinterpret_cast<float4*>(&g_Wt[off]) = *reinterpret_cast<float4*>(outv);
}

// ---------------- main GEMM: mma.sync m16n8k16, cp.async, BK=64 ------------
// 2 CTAs/SM x 8 warps (warp tile 32x64); 3 stages; wait_group 1 discipline.
static constexpr int BM = 128, BN = 128, BK = 64, STAGES = 3;
static constexpr int ROW_HALFS = 72;                 // 64 data + 8 pad -> 144B stride
static constexpr int ROW_BYTES = ROW_HALFS * 2;      // 144 (mod 128 = 16: LDSM conflict-free)
static constexpr int TILE_ROWS = BM;                 // per-operand rows per stage
static constexpr int OP_STAGE_BYTES = TILE_ROWS * ROW_BYTES;      // 18432
static constexpr int SB_OFF = STAGES * OP_STAGE_BYTES;            // 55296
static constexpr int GEMM_SMEM = 2 * STAGES * OP_STAGE_BYTES;     // 110592 (x2 CTA = 221184)
static constexpr int TM_TILES = M_DIM / BM;   // 64
static constexpr int TN_TILES = N_DIM / BN;   // 86
static constexpr int KITERS = K_DIM / BK;     // 64

__device__ __forceinline__ uint32_t smem_u32(const void* p) {
    uint32_t a;
    asm("{ .reg .u64 t; cvta.to.shared.u64 t, %1; cvt.u32.u64 %0, t; }" : "=r"(a) : "l"(p));
    return a;
}

#define CP_ASYNC_16(dst, src) \
    asm volatile("cp.async.cg.shared.global [%0], [%1], 16;" :: "r"(dst), "l"(src))
#define CP_ASYNC_COMMIT() asm volatile("cp.async.commit_group;")
#define CP_ASYNC_WAIT1()  asm volatile("cp.async.wait_group 1;")

#define LDSM_X4(r0, r1, r2, r3, addr) \
    asm volatile("ldmatrix.sync.aligned.m8n8.x4.shared.b16 {%0,%1,%2,%3}, [%4];" \
                 : "=r"(r0), "=r"(r1), "=r"(r2), "=r"(r3) : "r"(addr))

#define MMA_16816(c, a0, a1, a2, a3, b0, b1) \
    asm volatile("mma.sync.aligned.m16n8k16.row.col.f32.f16.f16.f32 " \
                 "{%0,%1,%2,%3}, {%4,%5,%6,%7}, {%8,%9}, {%0,%1,%2,%3};" \
                 : "+f"((c)[0]), "+f"((c)[1]), "+f"((c)[2]), "+f"((c)[3]) \
                 : "r"(a0), "r"(a1), "r"(a2), "r"(a3), "r"(b0), "r"(b1))

__global__ void __launch_bounds__(256, 2) gemm_kernel(float* __restrict__ out) {
    extern __shared__ __align__(128) char smem[];
    uint32_t sb = smem_u32(smem);
    int tid = threadIdx.x, wid = tid >> 5, lane = tid & 31;

    // GROUP_M=8 tile ordering for L2 reuse
    constexpr int GROUP_M = 8;
    int pid = blockIdx.x;
    int group_size = GROUP_M * TN_TILES;
    int group_id = pid / group_size;
    int pid_m = group_id * GROUP_M + (pid % GROUP_M);
    int pid_n = (pid % group_size) / GROUP_M;
    int m0 = pid_m * BM, n0 = pid_n * BN;

    // warp grid 4 (m) x 2 (n); warp tile 32 x 64
    int wm = wid & 3, wn = wid >> 2;
    int m0w = wm * 32, n0w = wn * 64;

    // --- cp.async chunk ownership ---
    // per operand per stage: 128 rows x 8 chunks(16B) = 1024 chunks; 256 thr x 4 each
    // thread base: row = tid>>3 (0..31), chunk col = tid&7; j in 0..3 adds 32 rows
    int r0 = tid >> 3, c0 = tid & 7;
    const __half* gA = &g_Ah[(size_t)(m0 + r0) * K_DIM + c0 * 8];
    const __half* gB = &g_Wt[(size_t)(n0 + r0) * K_DIM + c0 * 8];
    uint32_t sA = sb + r0 * ROW_BYTES + c0 * 16;
    uint32_t sB = sb + SB_OFF + r0 * ROW_BYTES + c0 * 16;
    constexpr size_t GROW = (size_t)32 * K_DIM;     // 32-row gmem step (halfs)
    constexpr uint32_t SROW = 32 * ROW_BYTES;       // 32-row smem step

    // --- ldmatrix per-lane base addresses (stage-relative) ---
    int lrow = lane & 15;
    int lcol8 = lane >> 4;         // 0/1 -> k offset 0/8
    uint32_t aAddrBase = sb + (m0w + lrow) * ROW_BYTES + lcol8 * 16;
    uint32_t bAddrBase = sb + SB_OFF + (n0w + lrow) * ROW_BYTES + lcol8 * 16;

    float acc[2][8][4];
#pragma unroll
    for (int mt = 0; mt < 2; mt++)
#pragma unroll
        for (int nt = 0; nt < 8; nt++)
#pragma unroll
            for (int j = 0; j < 4; j++) acc[mt][nt][j] = 0.f;

    // --- prologue: stages 0,1 ---
#pragma unroll
    for (int s = 0; s < STAGES - 1; s++) {
        int koff = s * BK;
        uint32_t so = s * OP_STAGE_BYTES;
#pragma unroll
        for (int j = 0; j < 4; j++) {
            CP_ASYNC_16(sA + so + j * SROW, gA + koff + j * GROW);
            CP_ASYNC_16(sB + so + j * SROW, gB + koff + j * GROW);
        }
        CP_ASYNC_COMMIT();
    }

    for (int kt = 0; kt < KITERS; kt++) {
        CP_ASYNC_WAIT1();            // group kt retired -> stage kt%3 ready
        __syncthreads();             // all warps done with stage (kt-1)%3

        if (kt + STAGES - 1 < KITERS) {
            int s = (kt + STAGES - 1) % STAGES;     // == (kt-1)%3, just released
            int koff = (kt + STAGES - 1) * BK;
            uint32_t so = s * OP_STAGE_BYTES;
#pragma unroll
            for (int j = 0; j < 4; j++) {
                CP_ASYNC_16(sA + so + j * SROW, gA + koff + j * GROW);
                CP_ASYNC_16(sB + so + j * SROW, gB + koff + j * GROW);
            }
            CP_ASYNC_COMMIT();
        } else {
            CP_ASYNC_COMMIT();
        }

        uint32_t so = (kt % STAGES) * OP_STAGE_BYTES;
#pragma unroll
        for (int ks = 0; ks < 4; ks++) {            // 4 x k16 within BK=64
            uint32_t kOff = ks * 32;                // 16 halfs = 32 bytes
            uint32_t a_frag[2][4];
#pragma unroll
            for (int mt = 0; mt < 2; mt++)
                LDSM_X4(a_frag[mt][0], a_frag[mt][1], a_frag[mt][2], a_frag[mt][3],
                        aAddrBase + so + mt * 16 * ROW_BYTES + kOff);
#pragma unroll
            for (int nq = 0; nq < 4; nq++) {        // 16 n per ldmatrix.x4
                uint32_t b0, b1, b2, b3;
                LDSM_X4(b0, b1, b2, b3, bAddrBase + so + nq * 16 * ROW_BYTES + kOff);
#pragma unroll
                for (int mt = 0; mt < 2; mt++) {
                    MMA_16816(acc[mt][2 * nq], a_frag[mt][0], a_frag[mt][1],
                              a_frag[mt][2], a_frag[mt][3], b0, b2);
                    MMA_16816(acc[mt][2 * nq + 1], a_frag[mt][0], a_frag[mt][1],
                              a_frag[mt][2], a_frag[mt][3], b1, b3);
                }
            }
        }
    }

    // --- epilogue ---
    int gq = lane >> 2, t4 = lane & 3;
#pragma unroll
    for (int mt = 0; mt < 2; mt++) {
        int mrow0 = m0 + m0w + mt * 16 + gq;
#pragma unroll
        for (int nt = 0; nt < 8; nt++) {
            int ncol = n0 + n0w + nt * 8 + t4 * 2;
            float2 v0 = make_float2(acc[mt][nt][0], acc[mt][nt][1]);
            float2 v1 = make_float2(acc[mt][nt][2], acc[mt][nt][3]);
            *reinterpret_cast<float2*>(&out[(size_t)mrow0 * N_DIM + ncol]) = v0;
            *reinterpret_cast<float2*>(&out[(size_t)(mrow0 + 8) * N_DIM + ncol]) = v1;
        }
    }
}

// ---------------- host launch ----------------------------------------------
extern "C" void kernel_launch(void* const* d_in, const int* in_sizes, int n_in,
                              void* d_out, int out_size) {
    const float* A = (const float*)d_in[0];
    const int*   W = (const int*)d_in[1];
    const float* S = (const float*)d_in[2];
    const int*   Z = (const int*)d_in[3];
    float* out = (float*)d_out;

    cudaFuncSetAttribute(gemm_kernel, cudaFuncAttributeMaxDynamicSharedMemorySize, GEMM_SMEM);

    prep_kernel<<<A_BLOCKS + W_BLOCKS, 256>>>(A, W, S, Z);
    gemm_kernel<<<TM_TILES * TN_TILES, 256, GEMM_SMEM>>>(out);
}

// round 5
// speedup vs baseline: 1.2759x; 1.0366x over previous
#include <cuda_runtime.h>
#include <cuda_fp16.h>
#include <cstdint>

#define M_DIM 8192
#define K_DIM 4096
#define N_DIM 11008

// ---------------- scratch (device globals; no runtime allocation) ----------
__device__ __half g_Ah[(size_t)M_DIM * K_DIM];   // A in fp16, [M, K] row-major
__device__ __half g_Wt[(size_t)N_DIM * K_DIM];   // W^T dequant fp16, [N, K] row-major

// ---------------- fused pre-pass: A fp32->fp16  +  int4 dequant->Wt[N,K] ---
static constexpr int A_BLOCKS = (int)(((size_t)M_DIM * K_DIM / 4) / 256);   // 32768
static constexpr int W_BLOCKS = (K_DIM / 64) * (N_DIM / 32);                 // 22016

__global__ void prep_kernel(const float* __restrict__ a, const int* __restrict__ w,
                            const float* __restrict__ scale, const int* __restrict__ zp) {
    __shared__ int sw[32][33];
    __shared__ float ssc[32];
    __shared__ float szp[32];
    int t = threadIdx.x;
    if (blockIdx.x < A_BLOCKS) {
        size_t i = (size_t)blockIdx.x * 256 + t;
        float4 v = reinterpret_cast<const float4*>(a)[i];
        __half2 h0 = __floats2half2_rn(v.x, v.y);
        __half2 h1 = __floats2half2_rn(v.z, v.w);
        uint2 o;
        o.x = *reinterpret_cast<uint32_t*>(&h0);
        o.y = *reinterpret_cast<uint32_t*>(&h1);
        reinterpret_cast<uint2*>(g_Ah)[i] = o;
        return;
    }
    int b = blockIdx.x - A_BLOCKS;
    int kt = b & 63;                   // 64 k per tile; group = kt>>1 (gs=128)
    int nt = b >> 6;
    int kp0 = kt * 32, n0 = nt * 32;
    int g = kt >> 1;
    for (int i = t; i < 1024; i += 256) {
        int r = i >> 5, c = i & 31;
        sw[r][c] = w[(size_t)(kp0 + r) * N_DIM + (n0 + c)];
    }
    if (t < 32) {
        ssc[t] = scale[(size_t)g * N_DIM + n0 + t];
        szp[t] = (float)zp[(size_t)g * N_DIM + n0 + t];
    }
    __syncthreads();
    int nl = t >> 3;
    int kq = (t & 7) * 4;
    float sc = ssc[nl], z = szp[nl];
    __half2 outv[4];
#pragma unroll
    for (int j = 0; j < 4; j++) {
        int wv = sw[kq + j][nl];
        outv[j] = __floats2half2_rn(((float)(wv & 0xF) - z) * sc,
                                    ((float)((wv >> 4) & 0xF) - z) * sc);
    }
    size_t off = (size_t)(n0 + nl) * K_DIM + (size_t)kt * 64 + kq * 2;
    *reinterpret_cast<float4*>(&g_Wt[off]) = *reinterpret_cast<float4*>(outv);
}

// ---------------- main GEMM: mma.sync m16n8k16, cp.async, BK=64 ------------
// 2 CTAs/SM x 8 warps (warp tile 32x64); 3 stages; wait_group 1;
// software-pipelined fragments (A double-buffered per k16, B per step).
static constexpr int BM = 128, BN = 128, BK = 64, STAGES = 3;
static constexpr int ROW_HALFS = 72;                 // 64 data + 8 pad -> 144B stride
static constexpr int ROW_BYTES = ROW_HALFS * 2;      // 144 (mod 128 = 16: LDSM conflict-free)
static constexpr int OP_STAGE_BYTES = BM * ROW_BYTES;             // 18432
static constexpr int SB_OFF = STAGES * OP_STAGE_BYTES;            // 55296
static constexpr int GEMM_SMEM = 2 * STAGES * OP_STAGE_BYTES;     // 110592 (x2 CTA = 221184)
static constexpr int TM_TILES = M_DIM / BM;   // 64
static constexpr int TN_TILES = N_DIM / BN;   // 86
static constexpr int KITERS = K_DIM / BK;     // 64

__device__ __forceinline__ uint32_t smem_u32(const void* p) {
    uint32_t a;
    asm("{ .reg .u64 t; cvta.to.shared.u64 t, %1; cvt.u32.u64 %0, t; }" : "=r"(a) : "l"(p));
    return a;
}

#define CP_ASYNC_16(dst, src) \
    asm volatile("cp.async.cg.shared.global [%0], [%1], 16;" :: "r"(dst), "l"(src))
#define CP_ASYNC_COMMIT() asm volatile("cp.async.commit_group;")
#define CP_ASYNC_WAIT1()  asm volatile("cp.async.wait_group 1;")

#define LDSM_X4(r0, r1, r2, r3, addr) \
    asm volatile("ldmatrix.sync.aligned.m8n8.x4.shared.b16 {%0,%1,%2,%3}, [%4];" \
                 : "=r"(r0), "=r"(r1), "=r"(r2), "=r"(r3) : "r"(addr))

#define MMA_16816(c, a0, a1, a2, a3, b0, b1) \
    asm volatile("mma.sync.aligned.m16n8k16.row.col.f32.f16.f16.f32 " \
                 "{%0,%1,%2,%3}, {%4,%5,%6,%7}, {%8,%9}, {%0,%1,%2,%3};" \
                 : "+f"((c)[0]), "+f"((c)[1]), "+f"((c)[2]), "+f"((c)[3]) \
                 : "r"(a0), "r"(a1), "r"(a2), "r"(a3), "r"(b0), "r"(b1))

__global__ void __launch_bounds__(256, 2) gemm_kernel(float* __restrict__ out) {
    extern __shared__ __align__(128) char smem[];
    uint32_t sb = smem_u32(smem);
    int tid = threadIdx.x, wid = tid >> 5, lane = tid & 31;

    // GROUP_M=8 tile ordering for L2 reuse
    constexpr int GROUP_M = 8;
    int pid = blockIdx.x;
    int group_size = GROUP_M * TN_TILES;
    int group_id = pid / group_size;
    int pid_m = group_id * GROUP_M + (pid % GROUP_M);
    int pid_n = (pid % group_size) / GROUP_M;
    int m0 = pid_m * BM, n0 = pid_n * BN;

    // warp grid 4 (m) x 2 (n); warp tile 32 x 64
    int wm = wid & 3, wn = wid >> 2;
    int m0w = wm * 32, n0w = wn * 64;

    // --- cp.async chunk ownership: 128 rows x 8 chunks(16B); 256 thr x 4 ---
    int r0 = tid >> 3, c0 = tid & 7;
    const __half* gA = &g_Ah[(size_t)(m0 + r0) * K_DIM + c0 * 8];
    const __half* gB = &g_Wt[(size_t)(n0 + r0) * K_DIM + c0 * 8];
    uint32_t sA = sb + r0 * ROW_BYTES + c0 * 16;
    uint32_t sB = sb + SB_OFF + r0 * ROW_BYTES + c0 * 16;
    constexpr size_t GROW = (size_t)32 * K_DIM;     // 32-row gmem step (halfs)
    constexpr uint32_t SROW = 32 * ROW_BYTES;       // 32-row smem step

    // --- ldmatrix per-lane base addresses (stage-relative) ---
    int lrow = lane & 15;
    int lcol8 = lane >> 4;         // 0/1 -> k offset 0/8
    uint32_t aAddrBase = sb + (m0w + lrow) * ROW_BYTES + lcol8 * 16;
    uint32_t bAddrBase = sb + SB_OFF + (n0w + lrow) * ROW_BYTES + lcol8 * 16;

    float acc[2][8][4];
#pragma unroll
    for (int mt = 0; mt < 2; mt++)
#pragma unroll
        for (int nt = 0; nt < 8; nt++)
#pragma unroll
            for (int j = 0; j < 4; j++) acc[mt][nt][j] = 0.f;

    // --- prologue: stages 0,1 ---
#pragma unroll
    for (int s = 0; s < STAGES - 1; s++) {
        int koff = s * BK;
        uint32_t so = s * OP_STAGE_BYTES;
#pragma unroll
        for (int j = 0; j < 4; j++) {
            CP_ASYNC_16(sA + so + j * SROW, gA + koff + j * GROW);
            CP_ASYNC_16(sB + so + j * SROW, gB + koff + j * GROW);
        }
        CP_ASYNC_COMMIT();
    }

    for (int kt = 0; kt < KITERS; kt++) {
        CP_ASYNC_WAIT1();            // group kt retired -> stage kt%3 ready
        __syncthreads();             // all warps done with stage (kt-1)%3

        uint32_t so = (kt % STAGES) * OP_STAGE_BYTES;
        uint32_t aB = aAddrBase + so, bB = bAddrBase + so;

        // preload first fragments of this stage (only exposed LDSM latency)
        uint32_t af[2][2][4];        // [k16 buf][mt][frag]
        uint32_t bf[2][4];           // [step buf][frag]
        LDSM_X4(af[0][0][0], af[0][0][1], af[0][0][2], af[0][0][3], aB);
        LDSM_X4(af[0][1][0], af[0][1][1], af[0][1][2], af[0][1][3], aB + 16 * ROW_BYTES);
        LDSM_X4(bf[0][0], bf[0][1], bf[0][2], bf[0][3], bB);

        // issue next stage's cp.async (into just-released slot)
        if (kt + STAGES - 1 < KITERS) {
            int s = (kt + STAGES - 1) % STAGES;
            int koff = (kt + STAGES - 1) * BK;
            uint32_t soN = s * OP_STAGE_BYTES;
#pragma unroll
            for (int j = 0; j < 4; j++) {
                CP_ASYNC_16(sA + soN + j * SROW, gA + koff + j * GROW);
                CP_ASYNC_16(sB + soN + j * SROW, gB + koff + j * GROW);
            }
            CP_ASYNC_COMMIT();
        } else {
            CP_ASYNC_COMMIT();
        }

        // 16 software-pipelined (k16, nq) steps
#pragma unroll
        for (int s = 0; s < 16; s++) {
            const int ks = s >> 2, nq = s & 3;
            const int cb = ks & 1, sbuf = s & 1;
            if (nq == 0 && ks < 3) {     // prefetch next k16's A frags
                const int kn = ks + 1, an = kn & 1;
                LDSM_X4(af[an][0][0], af[an][0][1], af[an][0][2], af[an][0][3],
                        aB + kn * 32);
                LDSM_X4(af[an][1][0], af[an][1][1], af[an][1][2], af[an][1][3],
                        aB + 16 * ROW_BYTES + kn * 32);
            }
            if (s < 15) {                // prefetch next step's B frags
                const int s2 = s + 1, ks2 = s2 >> 2, nq2 = s2 & 3, bn = s2 & 1;
                LDSM_X4(bf[bn][0], bf[bn][1], bf[bn][2], bf[bn][3],
                        bB + nq2 * 16 * ROW_BYTES + ks2 * 32);
            }
#pragma unroll
            for (int mt = 0; mt < 2; mt++) {
                MMA_16816(acc[mt][2 * nq], af[cb][mt][0], af[cb][mt][1],
                          af[cb][mt][2], af[cb][mt][3], bf[sbuf][0], bf[sbuf][2]);
                MMA_16816(acc[mt][2 * nq + 1], af[cb][mt][0], af[cb][mt][1],
                          af[cb][mt][2], af[cb][mt][3], bf[sbuf][1], bf[sbuf][3]);
            }
        }
    }

    // --- epilogue ---
    int gq = lane >> 2, t4 = lane & 3;
#pragma unroll
    for (int mt = 0; mt < 2; mt++) {
        int mrow0 = m0 + m0w + mt * 16 + gq;
#pragma unroll
        for (int nt = 0; nt < 8; nt++) {
            int ncol = n0 + n0w + nt * 8 + t4 * 2;
            float2 v0 = make_float2(acc[mt][nt][0], acc[mt][nt][1]);
            float2 v1 = make_float2(acc[mt][nt][2], acc[mt][nt][3]);
            *reinterpret_cast<float2*>(&out[(size_t)mrow0 * N_DIM + ncol]) = v0;
            *reinterpret_cast<float2*>(&out[(size_t)(mrow0 + 8) * N_DIM + ncol]) = v1;
        }
    }
}

// ---------------- host launch ----------------------------------------------
extern "C" void kernel_launch(void* const* d_in, const int* in_sizes, int n_in,
                              void* d_out, int out_size) {
    const float* A = (const float*)d_in[0];
    const int*   W = (const int*)d_in[1];
    const float* S = (const float*)d_in[2];
    const int*   Z = (const int*)d_in[3];
    float* out = (float*)d_out;

    cudaFuncSetAttribute(gemm_kernel, cudaFuncAttributeMaxDynamicSharedMemorySize, GEMM_SMEM);

    prep_kernel<<<A_BLOCKS + W_BLOCKS, 256>>>(A, W, S, Z);
    gemm_kernel<<<TM_TILES * TN_TILES, 256, GEMM_SMEM>>>(out);
}

// round 6
// speedup vs baseline: 1.4597x; 1.1440x over previous
#include <cuda_runtime.h>
#include <cuda_fp16.h>
#include <cstdint>

#define M_DIM 8192
#define K_DIM 4096
#define N_DIM 11008

// ---------------- scratch (device globals; no runtime allocation) ----------
__device__ __half g_Ah[(size_t)M_DIM * K_DIM];   // A in fp16, [M, K] row-major
__device__ __half g_Wt[(size_t)N_DIM * K_DIM];   // W^T dequant fp16, [N, K] row-major

// ---------------- fused pre-pass: A fp32->fp16  +  int4 dequant->Wt[N,K] ---
static constexpr int A_BLOCKS = (int)(((size_t)M_DIM * K_DIM / 4) / 256);   // 32768
static constexpr int W_BLOCKS = (K_DIM / 64) * (N_DIM / 32);                 // 22016

__global__ void prep_kernel(const float* __restrict__ a, const int* __restrict__ w,
                            const float* __restrict__ scale, const int* __restrict__ zp) {
    __shared__ int sw[32][33];
    __shared__ float ssc[32];
    __shared__ float szp[32];
    int t = threadIdx.x;
    if (blockIdx.x < A_BLOCKS) {
        size_t i = (size_t)blockIdx.x * 256 + t;
        float4 v = reinterpret_cast<const float4*>(a)[i];
        __half2 h0 = __floats2half2_rn(v.x, v.y);
        __half2 h1 = __floats2half2_rn(v.z, v.w);
        uint2 o;
        o.x = *reinterpret_cast<uint32_t*>(&h0);
        o.y = *reinterpret_cast<uint32_t*>(&h1);
        reinterpret_cast<uint2*>(g_Ah)[i] = o;
        return;
    }
    int b = blockIdx.x - A_BLOCKS;
    int kt = b & 63;                   // 64 k per tile; group = kt>>1 (gs=128)
    int nt = b >> 6;
    int kp0 = kt * 32, n0 = nt * 32;
    int g = kt >> 1;
    for (int i = t; i < 1024; i += 256) {
        int r = i >> 5, c = i & 31;
        sw[r][c] = w[(size_t)(kp0 + r) * N_DIM + (n0 + c)];
    }
    if (t < 32) {
        ssc[t] = scale[(size_t)g * N_DIM + n0 + t];
        szp[t] = (float)zp[(size_t)g * N_DIM + n0 + t];
    }
    __syncthreads();
    int nl = t >> 3;
    int kq = (t & 7) * 4;
    float sc = ssc[nl], z = szp[nl];
    __half2 outv[4];
#pragma unroll
    for (int j = 0; j < 4; j++) {
        int wv = sw[kq + j][nl];
        outv[j] = __floats2half2_rn(((float)(wv & 0xF) - z) * sc,
                                    ((float)((wv >> 4) & 0xF) - z) * sc);
    }
    size_t off = (size_t)(n0 + nl) * K_DIM + (size_t)kt * 64 + kq * 2;
    *reinterpret_cast<float4*>(&g_Wt[off]) = *reinterpret_cast<float4*>(outv);
}

// ---------------- main GEMM: mma.sync m16n8k16, mbarrier async pipeline ----
// 2 CTAs/SM x 8 warps (warp tile 32x64); 3 stages; NO __syncthreads in loop:
// full[s] flips via cp.async.mbarrier.arrive.noinc (256 per-thread arrivals),
// empty[s] flips via per-thread mbarrier.arrive after last read of stage.
static constexpr int BM = 128, BN = 128, BK = 64, STAGES = 3;
static constexpr int ROW_HALFS = 72;                 // 64 data + 8 pad -> 144B stride
static constexpr int ROW_BYTES = ROW_HALFS * 2;      // 144 (mod 128 = 16: LDSM conflict-free)
static constexpr int OP_STAGE_BYTES = BM * ROW_BYTES;             // 18432
static constexpr int SB_OFF = STAGES * OP_STAGE_BYTES;            // 55296
static constexpr int MBAR_OFF = 2 * STAGES * OP_STAGE_BYTES;      // 110592
static constexpr int GEMM_SMEM = MBAR_OFF + 64;                   // 110656 (x2 CTA fits 228KB)
static constexpr int TM_TILES = M_DIM / BM;   // 64
static constexpr int TN_TILES = N_DIM / BN;   // 86
static constexpr int KITERS = K_DIM / BK;     // 64

__device__ __forceinline__ uint32_t smem_u32(const void* p) {
    uint32_t a;
    asm("{ .reg .u64 t; cvta.to.shared.u64 t, %1; cvt.u32.u64 %0, t; }" : "=r"(a) : "l"(p));
    return a;
}

#define CP_ASYNC_16(dst, src) \
    asm volatile("cp.async.cg.shared.global [%0], [%1], 16;" :: "r"(dst), "l"(src))

#define CP_ASYNC_MBAR_ARRIVE(mbar) \
    asm volatile("cp.async.mbarrier.arrive.noinc.shared.b64 [%0];" :: "r"((uint32_t)(mbar)) : "memory")

#define MBARRIER_INIT(addr, cnt) \
    asm volatile("mbarrier.init.shared.b64 [%0], %1;" :: "r"((uint32_t)(addr)), "r"((uint32_t)(cnt)) : "memory")

#define MBARRIER_ARRIVE(addr) \
    asm volatile("mbarrier.arrive.shared.b64 _, [%0];" :: "r"((uint32_t)(addr)) : "memory")

#define MBARRIER_WAIT_PARITY(addr, parity) do { \
    uint32_t _m = (uint32_t)(addr); \
    uint32_t _p = (uint32_t)(parity); \
    uint32_t _done; \
    asm volatile("{\n\t.reg .pred p;\n\t" \
        "mbarrier.try_wait.parity.acquire.cta.shared::cta.b64 p, [%1], %2;\n\t" \
        "selp.b32 %0, 1, 0, p;\n\t}" : "=r"(_done) : "r"(_m), "r"(_p) : "memory"); \
    if (!_done) { \
        asm volatile("{\n\t.reg .pred P1;\n\t" \
            "WL_%=:\n\t" \
            "mbarrier.try_wait.parity.acquire.cta.shared::cta.b64 P1, [%0], %1, 0x989680;\n\t" \
            "@P1 bra.uni WD_%=;\n\t" \
            "bra.uni WL_%=;\n\t" \
            "WD_%=:\n\t}" :: "r"(_m), "r"(_p) : "memory"); \
    } \
} while (0)

#define LDSM_X4(r0, r1, r2, r3, addr) \
    asm volatile("ldmatrix.sync.aligned.m8n8.x4.shared.b16 {%0,%1,%2,%3}, [%4];" \
                 : "=r"(r0), "=r"(r1), "=r"(r2), "=r"(r3) : "r"(addr))

#define MMA_16816(c, a0, a1, a2, a3, b0, b1) \
    asm volatile("mma.sync.aligned.m16n8k16.row.col.f32.f16.f16.f32 " \
                 "{%0,%1,%2,%3}, {%4,%5,%6,%7}, {%8,%9}, {%0,%1,%2,%3};" \
                 : "+f"((c)[0]), "+f"((c)[1]), "+f"((c)[2]), "+f"((c)[3]) \
                 : "r"(a0), "r"(a1), "r"(a2), "r"(a3), "r"(b0), "r"(b1))

__global__ void __launch_bounds__(256, 2) gemm_kernel(float* __restrict__ out) {
    extern __shared__ __align__(128) char smem[];
    uint32_t sb = smem_u32(smem);
    int tid = threadIdx.x, wid = tid >> 5, lane = tid & 31;

    // mbarriers: full[s] @ MBAR_OFF + 8s ; empty[s] @ MBAR_OFF + 24 + 8s
    uint32_t mbFull = sb + MBAR_OFF;
    uint32_t mbEmpty = sb + MBAR_OFF + 24;
    if (tid == 0) {
#pragma unroll
        for (int s = 0; s < STAGES; s++) {
            MBARRIER_INIT(mbFull + 8 * s, 256);    // 256 cp-completion arrivals
            MBARRIER_INIT(mbEmpty + 8 * s, 256);   // 256 reader arrivals
        }
    }
    __syncthreads();   // only barrier in the kernel

    // GROUP_M=8 tile ordering for L2 reuse
    constexpr int GROUP_M = 8;
    int pid = blockIdx.x;
    int group_size = GROUP_M * TN_TILES;
    int group_id = pid / group_size;
    int pid_m = group_id * GROUP_M + (pid % GROUP_M);
    int pid_n = (pid % group_size) / GROUP_M;
    int m0 = pid_m * BM, n0 = pid_n * BN;

    // warp grid 4 (m) x 2 (n); warp tile 32 x 64
    int wm = wid & 3, wn = wid >> 2;
    int m0w = wm * 32, n0w = wn * 64;

    // --- cp.async chunk ownership: 128 rows x 8 chunks(16B); 256 thr x 4 ---
    int r0 = tid >> 3, c0 = tid & 7;
    const __half* gA = &g_Ah[(size_t)(m0 + r0) * K_DIM + c0 * 8];
    const __half* gB = &g_Wt[(size_t)(n0 + r0) * K_DIM + c0 * 8];
    uint32_t sA = sb + r0 * ROW_BYTES + c0 * 16;
    uint32_t sB = sb + SB_OFF + r0 * ROW_BYTES + c0 * 16;
    constexpr size_t GROW = (size_t)32 * K_DIM;     // 32-row gmem step (halfs)
    constexpr uint32_t SROW = 32 * ROW_BYTES;       // 32-row smem step

    // --- ldmatrix per-lane base addresses (stage-relative) ---
    int lrow = lane & 15;
    int lcol8 = lane >> 4;         // 0/1 -> k offset 0/8
    uint32_t aAddrBase = sb + (m0w + lrow) * ROW_BYTES + lcol8 * 16;
    uint32_t bAddrBase = sb + SB_OFF + (n0w + lrow) * ROW_BYTES + lcol8 * 16;

    float acc[2][8][4];
#pragma unroll
    for (int mt = 0; mt < 2; mt++)
#pragma unroll
        for (int nt = 0; nt < 8; nt++)
#pragma unroll
            for (int j = 0; j < 4; j++) acc[mt][nt][j] = 0.f;

    // --- prologue: fill stages 0,1 (no empty wait: first fills) ---
#pragma unroll
    for (int s = 0; s < STAGES - 1; s++) {
        int koff = s * BK;
        uint32_t so = s * OP_STAGE_BYTES;
#pragma unroll
        for (int j = 0; j < 4; j++) {
            CP_ASYNC_16(sA + so + j * SROW, gA + koff + j * GROW);
            CP_ASYNC_16(sB + so + j * SROW, gB + koff + j * GROW);
        }
        CP_ASYNC_MBAR_ARRIVE(mbFull + 8 * s);
    }

    // pipeline state: sc = consume stage, pc = full parity for this round;
    // sf = fill stage for iter kt+2; pe = empty parity for current fill use.
    int sc = 0, pc = 0;
    int sf = 2, pe = 0;

    for (int kt = 0; kt < KITERS; kt++) {
        MBARRIER_WAIT_PARITY(mbFull + 8 * sc, pc);   // stage sc ready (acquire)

        uint32_t so = sc * OP_STAGE_BYTES;
        uint32_t aB = aAddrBase + so, bB = bAddrBase + so;

        // preload first fragments of this stage
        uint32_t af[2][2][4];        // [k16 buf][mt][frag]
        uint32_t bf[2][4];           // [step buf][frag]
        LDSM_X4(af[0][0][0], af[0][0][1], af[0][0][2], af[0][0][3], aB);
        LDSM_X4(af[0][1][0], af[0][1][1], af[0][1][2], af[0][1][3], aB + 16 * ROW_BYTES);
        LDSM_X4(bf[0][0], bf[0][1], bf[0][2], bf[0][3], bB);

        // fill stage sf for iter kt+2 (skip empty wait on each stage's 1st fill)
        if (kt + 2 < KITERS) {
            if (kt > 0) MBARRIER_WAIT_PARITY(mbEmpty + 8 * sf, pe);
            int koff = (kt + 2) * BK;
            uint32_t soN = sf * OP_STAGE_BYTES;
#pragma unroll
            for (int j = 0; j < 4; j++) {
                CP_ASYNC_16(sA + soN + j * SROW, gA + koff + j * GROW);
                CP_ASYNC_16(sB + soN + j * SROW, gB + koff + j * GROW);
            }
            CP_ASYNC_MBAR_ARRIVE(mbFull + 8 * sf);
        }

        // 16 software-pipelined (k16, nq) steps
#pragma unroll
        for (int s = 0; s < 16; s++) {
            const int ks = s >> 2, nq = s & 3;
            const int cb = ks & 1, sbuf = s & 1;
            if (nq == 0 && ks < 3) {     // prefetch next k16's A frags
                const int kn = ks + 1, an = kn & 1;
                LDSM_X4(af[an][0][0], af[an][0][1], af[an][0][2], af[an][0][3],
                        aB + kn * 32);
                LDSM_X4(af[an][1][0], af[an][1][1], af[an][1][2], af[an][1][3],
                        aB + 16 * ROW_BYTES + kn * 32);
            }
            if (s < 15) {                // prefetch next step's B frags
                const int s2 = s + 1, ks2 = s2 >> 2, nq2 = s2 & 3, bn = s2 & 1;
                LDSM_X4(bf[bn][0], bf[bn][1], bf[bn][2], bf[bn][3],
                        bB + nq2 * 16 * ROW_BYTES + ks2 * 32);
            }
#pragma unroll
            for (int mt = 0; mt < 2; mt++) {
                MMA_16816(acc[mt][2 * nq], af[cb][mt][0], af[cb][mt][1],
                          af[cb][mt][2], af[cb][mt][3], bf[sbuf][0], bf[sbuf][2]);
                MMA_16816(acc[mt][2 * nq + 1], af[cb][mt][0], af[cb][mt][1],
                          af[cb][mt][2], af[cb][mt][3], bf[sbuf][1], bf[sbuf][3]);
            }
        }

        // all reads of stage sc consumed into regs (last MMA issue gates them)
        MBARRIER_ARRIVE(mbEmpty + 8 * sc);

        // advance stage counters / parities
        // pe toggles between kt=3r+2 and kt=3r+3... empty wait parity:
        // wait for fill f=(kt+2)/3 uses parity (f-1)&1; toggles after kt%3==0 (kt>0)
        if (sc == 0 && kt > 0) pe ^= 1;
        if (++sc == STAGES) { sc = 0; pc ^= 1; }
        if (++sf == STAGES) { sf = 0; }
    }

    // --- epilogue ---
    int gq = lane >> 2, t4 = lane & 3;
#pragma unroll
    for (int mt = 0; mt < 2; mt++) {
        int mrow0 = m0 + m0w + mt * 16 + gq;
#pragma unroll
        for (int nt = 0; nt < 8; nt++) {
            int ncol = n0 + n0w + nt * 8 + t4 * 2;
            float2 v0 = make_float2(acc[mt][nt][0], acc[mt][nt][1]);
            float2 v1 = make_float2(acc[mt][nt][2], acc[mt][nt][3]);
            *reinterpret_cast<float2*>(&out[(size_t)mrow0 * N_DIM + ncol]) = v0;
            *reinterpret_cast<float2*>(&out[(size_t)(mrow0 + 8) * N_DIM + ncol]) = v1;
        }
    }
}

// ---------------- host launch ----------------------------------------------
extern "C" void kernel_launch(void* const* d_in, const int* in_sizes, int n_in,
                              void* d_out, int out_size) {
    const float* A = (const float*)d_in[0];
    const int*   W = (const int*)d_in[1];
    const float* S = (const float*)d_in[2];
    const int*   Z = (const int*)d_in[3];
    float* out = (float*)d_out;

    cudaFuncSetAttribute(gemm_kernel, cudaFuncAttributeMaxDynamicSharedMemorySize, GEMM_SMEM);

    prep_kernel<<<A_BLOCKS + W_BLOCKS, 256>>>(A, W, S, Z);
    gemm_kernel<<<TM_TILES * TN_TILES, 256, GEMM_SMEM>>>(out);
}

// round 7
// speedup vs baseline: 1.4647x; 1.0035x over previous
#include <cuda_runtime.h>
#include <cuda_fp16.h>
#include <cstdint>

#define M_DIM 8192
#define K_DIM 4096
#define N_DIM 11008

// ---------------- scratch (device globals; no runtime allocation) ----------
__device__ __half g_Ah[(size_t)M_DIM * K_DIM];   // A in fp16, [M, K] row-major
__device__ __half g_Wt[(size_t)N_DIM * K_DIM];   // W^T dequant fp16, [N, K] row-major

// ---------------- fused pre-pass: A fp32->fp16  +  int4 dequant->Wt[N,K] ---
// A part: each thread converts 2 independent float4s (MLP=2).
static constexpr int A_BLOCKS = (int)(((size_t)M_DIM * K_DIM / 4) / 512);   // 16384
static constexpr int W_BLOCKS = (K_DIM / 64) * (N_DIM / 32);                 // 22016

__global__ void prep_kernel(const float* __restrict__ a, const int* __restrict__ w,
                            const float* __restrict__ scale, const int* __restrict__ zp) {
    __shared__ int sw[32][33];
    __shared__ float ssc[32];
    __shared__ float szp[32];
    int t = threadIdx.x;
    if (blockIdx.x < A_BLOCKS) {
        size_t i0 = (size_t)blockIdx.x * 512 + t;
        size_t i1 = i0 + 256;
        float4 v0 = reinterpret_cast<const float4*>(a)[i0];
        float4 v1 = reinterpret_cast<const float4*>(a)[i1];
        __half2 h00 = __floats2half2_rn(v0.x, v0.y);
        __half2 h01 = __floats2half2_rn(v0.z, v0.w);
        __half2 h10 = __floats2half2_rn(v1.x, v1.y);
        __half2 h11 = __floats2half2_rn(v1.z, v1.w);
        uint2 o0, o1;
        o0.x = *reinterpret_cast<uint32_t*>(&h00);
        o0.y = *reinterpret_cast<uint32_t*>(&h01);
        o1.x = *reinterpret_cast<uint32_t*>(&h10);
        o1.y = *reinterpret_cast<uint32_t*>(&h11);
        reinterpret_cast<uint2*>(g_Ah)[i0] = o0;
        reinterpret_cast<uint2*>(g_Ah)[i1] = o1;
        return;
    }
    int b = blockIdx.x - A_BLOCKS;
    int kt = b & 63;                   // 64 k per tile; group = kt>>1 (gs=128)
    int nt = b >> 6;
    int kp0 = kt * 32, n0 = nt * 32;
    int g = kt >> 1;
    for (int i = t; i < 1024; i += 256) {
        int r = i >> 5, c = i & 31;
        sw[r][c] = w[(size_t)(kp0 + r) * N_DIM + (n0 + c)];
    }
    if (t < 32) {
        ssc[t] = scale[(size_t)g * N_DIM + n0 + t];
        szp[t] = (float)zp[(size_t)g * N_DIM + n0 + t];
    }
    __syncthreads();
    int nl = t >> 3;
    int kq = (t & 7) * 4;
    float sc = ssc[nl], z = szp[nl];
    __half2 outv[4];
#pragma unroll
    for (int j = 0; j < 4; j++) {
        int wv = sw[kq + j][nl];
        outv[j] = __floats2half2_rn(((float)(wv & 0xF) - z) * sc,
                                    ((float)((wv >> 4) & 0xF) - z) * sc);
    }
    size_t off = (size_t)(n0 + nl) * K_DIM + (size_t)kt * 64 + kq * 2;
    *reinterpret_cast<float4*>(&g_Wt[off]) = *reinterpret_cast<float4*>(outv);
}

// ---------------- main GEMM: mma.sync m16n8k16, mbarrier async pipeline ----
// 2 CTAs/SM x 8 warps (warp tile 32x64); 3 stages; no __syncthreads in loop.
static constexpr int BM = 128, BN = 128, BK = 64, STAGES = 3;
static constexpr int ROW_HALFS = 72;                 // 64 data + 8 pad -> 144B stride
static constexpr int ROW_BYTES = ROW_HALFS * 2;      // 144 (mod 128 = 16: LDSM conflict-free)
static constexpr int OP_STAGE_BYTES = BM * ROW_BYTES;             // 18432
static constexpr int SB_OFF = STAGES * OP_STAGE_BYTES;            // 55296
static constexpr int MBAR_OFF = 2 * STAGES * OP_STAGE_BYTES;      // 110592
static constexpr int GEMM_SMEM = MBAR_OFF + 64;                   // 110656 (x2 CTA fits 228KB)
static constexpr int TM_TILES = M_DIM / BM;   // 64
static constexpr int TN_TILES = N_DIM / BN;   // 86
static constexpr int KITERS = K_DIM / BK;     // 64

__device__ __forceinline__ uint32_t smem_u32(const void* p) {
    uint32_t a;
    asm("{ .reg .u64 t; cvta.to.shared.u64 t, %1; cvt.u32.u64 %0, t; }" : "=r"(a) : "l"(p));
    return a;
}

#define CP_ASYNC_16(dst, src) \
    asm volatile("cp.async.cg.shared.global [%0], [%1], 16;" :: "r"(dst), "l"(src))

#define CP_ASYNC_MBAR_ARRIVE(mbar) \
    asm volatile("cp.async.mbarrier.arrive.noinc.shared.b64 [%0];" :: "r"((uint32_t)(mbar)) : "memory")

#define MBARRIER_INIT(addr, cnt) \
    asm volatile("mbarrier.init.shared.b64 [%0], %1;" :: "r"((uint32_t)(addr)), "r"((uint32_t)(cnt)) : "memory")

#define MBARRIER_ARRIVE(addr) \
    asm volatile("mbarrier.arrive.shared.b64 _, [%0];" :: "r"((uint32_t)(addr)) : "memory")

// acquire wait: consumer side (generic LDS reads follow)
#define MBARRIER_WAIT_PARITY(addr, parity) do { \
    uint32_t _m = (uint32_t)(addr); \
    uint32_t _p = (uint32_t)(parity); \
    uint32_t _done; \
    asm volatile("{\n\t.reg .pred p;\n\t" \
        "mbarrier.try_wait.parity.acquire.cta.shared::cta.b64 p, [%1], %2;\n\t" \
        "selp.b32 %0, 1, 0, p;\n\t}" : "=r"(_done) : "r"(_m), "r"(_p) : "memory"); \
    if (!_done) { \
        asm volatile("{\n\t.reg .pred P1;\n\t" \
            "WL_%=:\n\t" \
            "mbarrier.try_wait.parity.acquire.cta.shared::cta.b64 P1, [%0], %1, 0x989680;\n\t" \
            "@P1 bra.uni WD_%=;\n\t" \
            "bra.uni WL_%=;\n\t" \
            "WD_%=:\n\t}" :: "r"(_m), "r"(_p) : "memory"); \
    } \
} while (0)

// relaxed wait: producer side only (post-wait smem writes are cp.async = async path)
#define MBARRIER_WAIT_PARITY_RELAXED(addr, parity) do { \
    uint32_t _m = (uint32_t)(addr); \
    uint32_t _p = (uint32_t)(parity); \
    uint32_t _done; \
    asm volatile("{\n\t.reg .pred p;\n\t" \
        "mbarrier.try_wait.parity.relaxed.cta.shared::cta.b64 p, [%1], %2;\n\t" \
        "selp.b32 %0, 1, 0, p;\n\t}" : "=r"(_done) : "r"(_m), "r"(_p) : "memory"); \
    if (!_done) { \
        asm volatile("{\n\t.reg .pred P1;\n\t" \
            "WL_%=:\n\t" \
            "mbarrier.try_wait.parity.relaxed.cta.shared::cta.b64 P1, [%0], %1, 0x989680;\n\t" \
            "@P1 bra.uni WD_%=;\n\t" \
            "bra.uni WL_%=;\n\t" \
            "WD_%=:\n\t}" :: "r"(_m), "r"(_p) : "memory"); \
    } \
} while (0)

#define LDSM_X4(r0, r1, r2, r3, addr) \
    asm volatile("ldmatrix.sync.aligned.m8n8.x4.shared.b16 {%0,%1,%2,%3}, [%4];" \
                 : "=r"(r0), "=r"(r1), "=r"(r2), "=r"(r3) : "r"(addr))

#define MMA_16816(c, a0, a1, a2, a3, b0, b1) \
    asm volatile("mma.sync.aligned.m16n8k16.row.col.f32.f16.f16.f32 " \
                 "{%0,%1,%2,%3}, {%4,%5,%6,%7}, {%8,%9}, {%0,%1,%2,%3};" \
                 : "+f"((c)[0]), "+f"((c)[1]), "+f"((c)[2]), "+f"((c)[3]) \
                 : "r"(a0), "r"(a1), "r"(a2), "r"(a3), "r"(b0), "r"(b1))

__global__ void __launch_bounds__(256, 2) gemm_kernel(float* __restrict__ out) {
    extern __shared__ __align__(128) char smem[];
    uint32_t sb = smem_u32(smem);
    int tid = threadIdx.x, wid = tid >> 5, lane = tid & 31;

    // mbarriers: full[s] @ MBAR_OFF + 8s ; empty[s] @ MBAR_OFF + 24 + 8s
    uint32_t mbFull = sb + MBAR_OFF;
    uint32_t mbEmpty = sb + MBAR_OFF + 24;
    if (tid == 0) {
#pragma unroll
        for (int s = 0; s < STAGES; s++) {
            MBARRIER_INIT(mbFull + 8 * s, 256);    // 256 cp-completion arrivals
            MBARRIER_INIT(mbEmpty + 8 * s, 256);   // 256 reader arrivals
        }
    }
    __syncthreads();   // only barrier in the kernel

    // GROUP_M=16 tile ordering for L2 reuse (64 M-tiles = 4 exact groups)
    constexpr int GROUP_M = 16;
    int pid = blockIdx.x;
    int group_size = GROUP_M * TN_TILES;
    int group_id = pid / group_size;
    int pid_m = group_id * GROUP_M + (pid % GROUP_M);
    int pid_n = (pid % group_size) / GROUP_M;
    int m0 = pid_m * BM, n0 = pid_n * BN;

    // warp grid 4 (m) x 2 (n); warp tile 32 x 64
    int wm = wid & 3, wn = wid >> 2;
    int m0w = wm * 32, n0w = wn * 64;

    // --- cp.async chunk ownership: 128 rows x 8 chunks(16B); 256 thr x 4 ---
    int r0 = tid >> 3, c0 = tid & 7;
    const __half* gA = &g_Ah[(size_t)(m0 + r0) * K_DIM + c0 * 8];
    const __half* gB = &g_Wt[(size_t)(n0 + r0) * K_DIM + c0 * 8];
    uint32_t sA = sb + r0 * ROW_BYTES + c0 * 16;
    uint32_t sB = sb + SB_OFF + r0 * ROW_BYTES + c0 * 16;
    constexpr size_t GROW = (size_t)32 * K_DIM;     // 32-row gmem step (halfs)
    constexpr uint32_t SROW = 32 * ROW_BYTES;       // 32-row smem step

    // --- ldmatrix per-lane base addresses (stage-relative) ---
    int lrow = lane & 15;
    int lcol8 = lane >> 4;         // 0/1 -> k offset 0/8
    uint32_t aAddrBase = sb + (m0w + lrow) * ROW_BYTES + lcol8 * 16;
    uint32_t bAddrBase = sb + SB_OFF + (n0w + lrow) * ROW_BYTES + lcol8 * 16;

    float acc[2][8][4];
#pragma unroll
    for (int mt = 0; mt < 2; mt++)
#pragma unroll
        for (int nt = 0; nt < 8; nt++)
#pragma unroll
            for (int j = 0; j < 4; j++) acc[mt][nt][j] = 0.f;

    // --- prologue: fill stages 0,1 (no empty wait: first fills) ---
#pragma unroll
    for (int s = 0; s < STAGES - 1; s++) {
        int koff = s * BK;
        uint32_t so = s * OP_STAGE_BYTES;
#pragma unroll
        for (int j = 0; j < 4; j++) {
            CP_ASYNC_16(sA + so + j * SROW, gA + koff + j * GROW);
            CP_ASYNC_16(sB + so + j * SROW, gB + koff + j * GROW);
        }
        CP_ASYNC_MBAR_ARRIVE(mbFull + 8 * s);
    }

    // pipeline state: sc = consume stage, pc = full parity for this round;
    // sf = fill stage for iter kt+2; pe = empty parity for current fill use.
    int sc = 0, pc = 0;
    int sf = 2, pe = 0;

    for (int kt = 0; kt < KITERS; kt++) {
        MBARRIER_WAIT_PARITY(mbFull + 8 * sc, pc);   // stage sc ready (acquire)

        uint32_t so = sc * OP_STAGE_BYTES;
        uint32_t aB = aAddrBase + so, bB = bAddrBase + so;

        // preload first fragments of this stage
        uint32_t af[2][2][4];        // [k16 buf][mt][frag]
        uint32_t bf[2][4];           // [step buf][frag]
        LDSM_X4(af[0][0][0], af[0][0][1], af[0][0][2], af[0][0][3], aB);
        LDSM_X4(af[0][1][0], af[0][1][1], af[0][1][2], af[0][1][3], aB + 16 * ROW_BYTES);
        LDSM_X4(bf[0][0], bf[0][1], bf[0][2], bf[0][3], bB);

        // fill stage sf for iter kt+2 (skip empty wait on each stage's 1st fill)
        if (kt + 2 < KITERS) {
            if (kt > 0) MBARRIER_WAIT_PARITY_RELAXED(mbEmpty + 8 * sf, pe);
            int koff = (kt + 2) * BK;
            uint32_t soN = sf * OP_STAGE_BYTES;
#pragma unroll
            for (int j = 0; j < 4; j++) {
                CP_ASYNC_16(sA + soN + j * SROW, gA + koff + j * GROW);
                CP_ASYNC_16(sB + soN + j * SROW, gB + koff + j * GROW);
            }
            CP_ASYNC_MBAR_ARRIVE(mbFull + 8 * sf);
        }

        // 16 software-pipelined (k16, nq) steps
#pragma unroll
        for (int s = 0; s < 16; s++) {
            const int ks = s >> 2, nq = s & 3;
            const int cb = ks & 1, sbuf = s & 1;
            if (nq == 0 && ks < 3) {     // prefetch next k16's A frags
                const int kn = ks + 1, an = kn & 1;
                LDSM_X4(af[an][0][0], af[an][0][1], af[an][0][2], af[an][0][3],
                        aB + kn * 32);
                LDSM_X4(af[an][1][0], af[an][1][1], af[an][1][2], af[an][1][3],
                        aB + 16 * ROW_BYTES + kn * 32);
            }
            if (s < 15) {                // prefetch next step's B frags
                const int s2 = s + 1, ks2 = s2 >> 2, nq2 = s2 & 3, bn = s2 & 1;
                LDSM_X4(bf[bn][0], bf[bn][1], bf[bn][2], bf[bn][3],
                        bB + nq2 * 16 * ROW_BYTES + ks2 * 32);
            }
#pragma unroll
            for (int mt = 0; mt < 2; mt++) {
                MMA_16816(acc[mt][2 * nq], af[cb][mt][0], af[cb][mt][1],
                          af[cb][mt][2], af[cb][mt][3], bf[sbuf][0], bf[sbuf][2]);
                MMA_16816(acc[mt][2 * nq + 1], af[cb][mt][0], af[cb][mt][1],
                          af[cb][mt][2], af[cb][mt][3], bf[sbuf][1], bf[sbuf][3]);
            }
        }

        // all reads of stage sc consumed into regs (last MMA issue gates them)
        MBARRIER_ARRIVE(mbEmpty + 8 * sc);

        // advance stage counters / parities
        if (sc == 0 && kt > 0) pe ^= 1;
        if (++sc == STAGES) { sc = 0; pc ^= 1; }
        if (++sf == STAGES) { sf = 0; }
    }

    // --- epilogue ---
    int gq = lane >> 2, t4 = lane & 3;
#pragma unroll
    for (int mt = 0; mt < 2; mt++) {
        int mrow0 = m0 + m0w + mt * 16 + gq;
#pragma unroll
        for (int nt = 0; nt < 8; nt++) {
            int ncol = n0 + n0w + nt * 8 + t4 * 2;
            float2 v0 = make_float2(acc[mt][nt][0], acc[mt][nt][1]);
            float2 v1 = make_float2(acc[mt][nt][2], acc[mt][nt][3]);
            *reinterpret_cast<float2*>(&out[(size_t)mrow0 * N_DIM + ncol]) = v0;
            *reinterpret_cast<float2*>(&out[(size_t)(mrow0 + 8) * N_DIM + ncol]) = v1;
        }
    }
}

// ---------------- host launch ----------------------------------------------
extern "C" void kernel_launch(void* const* d_in, const int* in_sizes, int n_in,
                              void* d_out, int out_size) {
    const float* A = (const float*)d_in[0];
    const int*   W = (const int*)d_in[1];
    const float* S = (const float*)d_in[2];
    const int*   Z = (const int*)d_in[3];
    float* out = (float*)d_out;

    cudaFuncSetAttribute(gemm_kernel, cudaFuncAttributeMaxDynamicSharedMemorySize, GEMM_SMEM);

    prep_kernel<<<A_BLOCKS + W_BLOCKS, 256>>>(A, W, S, Z);
    gemm_kernel<<<TM_TILES * TN_TILES, 256, GEMM_SMEM>>>(out);
}